// round 13
// baseline (speedup 1.0000x reference)
#include <cuda_runtime.h>
#include <cuda_fp16.h>
#include <cstdint>

// ============================================================================
// GraphSAGE fused layer — sm_103 baseline-PTX, warp-specialized pipeline (R9).
//
//   out = relu(concat(feature[nodes], mean(feature[neigh_idx],1)) @ W)
//   B=50000, S=10, D=128, H=128, K=256, N_NODES=100000.
//
// R9 deltas vs R8 (from ncu: L1 44.5%, issue 16.6% => producer-latency bound):
//   * feature table pre-converted to fp16 once per launch (streaming prep):
//     gather bytes halve => gather wavefronts 1408 -> 704 per tile
//   * 768 threads: 16 producer warps (2 rows each) + 8 consumer warps
//     (2 groups x 4, 32x32 tiles) — doubles latency-hiding on the gather side
//   * error: rounding features before the fp32 mean ~= rounding after
//     (u*rms/sqrt(10) either way); predicted rel_err ~4e-4 < 1e-3
// ============================================================================

static constexpr int BLK_M   = 32;
static constexpr int K_DIM   = 256;
static constexpr int H_OUT   = 128;
static constexpr int S_NEIGH = 10;
static constexpr int ROW_B   = 512;                   // 256 fp16, swizzled
static constexpr int W_BYTES = H_OUT * ROW_B;         // 65536
static constexpr int A_STAGE = BLK_M * ROW_B;         // 16384
static constexpr int NSTAGE  = 4;
static constexpr int N_THREADS = 768;
static constexpr int MAX_NODES = 100000;

// smem layout
static constexpr int SM_W     = 0;
static constexpr int SM_A     = SM_W + W_BYTES;           // 65536
static constexpr int SM_BAR   = SM_A + NSTAGE * A_STAGE;  // 131072
static constexpr int SM_TOTAL = SM_BAR + 80;

__device__ __align__(16) unsigned char g_wh[W_BYTES];
__device__ __align__(16) unsigned char g_feat_h[(size_t)MAX_NODES * 256];  // fp16 rows

// ---------------- helpers ----------------
__device__ __forceinline__ uint32_t smem_u32(const void* p) {
    uint32_t a;
    asm("{ .reg .u64 t; cvta.to.shared.u64 t, %1; cvt.u32.u64 %0, t; }"
        : "=r"(a) : "l"(p));
    return a;
}

// swizzled byte offset for element (row, kcol) in a 512B-pitch fp16 tile:
// 16B chunk index XORed with row%8
__host__ __device__ __forceinline__ uint32_t sw_off(int row, int kcol) {
    uint32_t byte  = (uint32_t)kcol * 2u;
    uint32_t chunk = (byte >> 4) ^ ((uint32_t)row & 7u);
    return (uint32_t)row * ROW_B + (chunk << 4) + (byte & 15u);
}

__device__ __forceinline__ void ldsm_x4(uint32_t (&d)[4], uint32_t addr) {
    asm volatile("ldmatrix.sync.aligned.m8n8.x4.shared.b16 {%0,%1,%2,%3}, [%4];"
                 : "=r"(d[0]), "=r"(d[1]), "=r"(d[2]), "=r"(d[3]) : "r"(addr));
}

__device__ __forceinline__ void mma_f16(float (&c)[4], const uint32_t (&a)[4],
                                        uint32_t b0, uint32_t b1) {
    asm volatile(
        "mma.sync.aligned.m16n8k16.row.col.f32.f16.f16.f32 "
        "{%0,%1,%2,%3}, {%4,%5,%6,%7}, {%8,%9}, {%0,%1,%2,%3};"
        : "+f"(c[0]), "+f"(c[1]), "+f"(c[2]), "+f"(c[3])
        : "r"(a[0]), "r"(a[1]), "r"(a[2]), "r"(a[3]), "r"(b0), "r"(b1));
}

#define MBARRIER_INIT(mbar, count) \
    asm volatile("mbarrier.init.shared.b64 [%0], %1;" \
                 :: "r"((uint32_t)(mbar)), "r"((uint32_t)(count)) : "memory")

#define MBARRIER_ARRIVE(mbar) \
    asm volatile("mbarrier.arrive.shared.b64 _, [%0];" \
                 :: "r"((uint32_t)(mbar)) : "memory")

#define MBARRIER_WAIT_PARITY(mbar, parity) do {                                  \
    uint32_t _m = (uint32_t)(mbar); uint32_t _p = (uint32_t)(parity);            \
    asm volatile(                                                                \
        "{\n\t.reg .pred P1;\n\t"                                                \
        "WAIT_LOOP_%=:\n\t"                                                      \
        "mbarrier.try_wait.parity.shared.b64 P1, [%0], %1;\n\t"                  \
        "@P1 bra.uni WAIT_DONE_%=;\n\t"                                          \
        "bra.uni WAIT_LOOP_%=;\n\t"                                              \
        "WAIT_DONE_%=:\n\t}"                                                     \
        :: "r"(_m), "r"(_p) : "memory");                                         \
} while (0)

#define FULL_BAR(sb, s)  ((sb) + SM_BAR + (s) * 16)
#define EMPTY_BAR(sb, s) ((sb) + SM_BAR + (s) * 16 + 8)

// ---------------- weight prep: transpose + fp16 + swizzle --------------------
__global__ void sage_prep_weight(const float* __restrict__ w) {
    int i = blockIdx.x * blockDim.x + threadIdx.x;
    if (i >= K_DIM * H_OUT) return;
    int k = i >> 7;        // weight row (0..255)
    int n = i & 127;       // weight col (0..127)
    *reinterpret_cast<__half*>(g_wh + sw_off(n, k)) = __float2half_rn(w[i]);
}

// ---------------- feature prep: fp32 -> fp16 table (streaming) ---------------
__global__ void sage_prep_feat(const float* __restrict__ feat, int n_elems) {
    int i = blockIdx.x * blockDim.x + threadIdx.x;   // one per 8 elements
    if (i >= n_elems / 8) return;
    const float4* f4 = reinterpret_cast<const float4*>(feat);
    float4 v0 = __ldg(f4 + 2 * i);
    float4 v1 = __ldg(f4 + 2 * i + 1);
    __half2 h0 = __floats2half2_rn(v0.x, v0.y);
    __half2 h1 = __floats2half2_rn(v0.z, v0.w);
    __half2 h2 = __floats2half2_rn(v1.x, v1.y);
    __half2 h3 = __floats2half2_rn(v1.z, v1.w);
    uint4 o;
    o.x = *reinterpret_cast<uint32_t*>(&h0);
    o.y = *reinterpret_cast<uint32_t*>(&h1);
    o.z = *reinterpret_cast<uint32_t*>(&h2);
    o.w = *reinterpret_cast<uint32_t*>(&h3);
    reinterpret_cast<uint4*>(g_feat_h)[i] = o;
}

// ---------------- fused persistent warp-specialized kernel -------------------
__global__ __launch_bounds__(N_THREADS, 1)
void sage_main(const int* __restrict__ nodes,
               const int* __restrict__ neigh,
               float* __restrict__ out,
               int B, int ntiles) {
    extern __shared__ __align__(16) char smem[];
    const uint32_t sb   = smem_u32(smem);
    const int tid  = threadIdx.x;
    const int wid  = tid >> 5;
    const int lane = tid & 31;

    if (tid == 0) {
        #pragma unroll
        for (int s = 0; s < NSTAGE; s++) {
            MBARRIER_INIT(FULL_BAR(sb, s), 512);   // 16 producer warps arrive
            MBARRIER_INIT(EMPTY_BAR(sb, s), 128);  // 4 consumer warps arrive
        }
    }

    // copy weight into smem once (swizzle preserved by linear copy)
    {
        const uint4* s0 = reinterpret_cast<const uint4*>(g_wh);
        uint4* d0 = reinterpret_cast<uint4*>(smem + SM_W);
        for (int i = tid; i < W_BYTES / 16; i += N_THREADS) d0[i] = s0[i];
    }
    __syncthreads();

    if (wid < 16) {
        // ============ PRODUCERS: 16 warps, 2 rows each ============
        // lane l covers cols 4l..4l+3 of a feature row (8B = uint2 of fp16)
        const uint2* f2 = reinterpret_cast<const uint2*>(g_feat_h);
        int stage = 0;
        uint32_t eph = 0xFu;   // per-stage empty parities (first pass free)

        // prologue: indices for first tile
        int selfi[2], idxv[2];
        {
            const int base = blockIdx.x * BLK_M;
            #pragma unroll
            for (int i = 0; i < 2; i++) {
                const int grow = base + wid * 2 + i;
                const int src = (grow < B) ? grow : 0;
                selfi[i] = __ldg(nodes + src);
                idxv[i] = (lane < S_NEIGH)
                          ? __ldg(neigh + (size_t)src * S_NEIGH + lane) : 0;
            }
        }

        for (int tile = blockIdx.x; tile < ntiles; tile += gridDim.x) {
            // --- self rows (fp16, kept packed) + neighbor accumulation ---
            uint2 sv[2];
            float4 acc[2];
            #pragma unroll
            for (int i = 0; i < 2; i++) {
                sv[i] = __ldg(f2 + (size_t)selfi[i] * 32 + lane);
                acc[i] = make_float4(0.f, 0.f, 0.f, 0.f);
            }

            // --- prefetch next tile's indices (hidden behind feature loads) ---
            int nselfi[2], nidxv[2];
            {
                const long nt = (long)tile + gridDim.x;
                const int nbase = (nt < ntiles) ? (int)nt * BLK_M : 0;
                #pragma unroll
                for (int i = 0; i < 2; i++) {
                    const int grow = nbase + wid * 2 + i;
                    const int src = (grow < B) ? grow : 0;
                    nselfi[i] = __ldg(nodes + src);
                    nidxv[i] = (lane < S_NEIGH)
                               ? __ldg(neigh + (size_t)src * S_NEIGH + lane) : 0;
                }
            }

            #pragma unroll
            for (int s = 0; s < S_NEIGH; s++) {
                #pragma unroll
                for (int i = 0; i < 2; i++) {
                    const int ni = __shfl_sync(0xffffffffu, idxv[i], s);
                    const uint2 v = __ldg(f2 + (size_t)ni * 32 + lane);
                    const __half2* hp = reinterpret_cast<const __half2*>(&v);
                    const float2 a = __half22float2(hp[0]);
                    const float2 b = __half22float2(hp[1]);
                    acc[i].x += a.x; acc[i].y += a.y;
                    acc[i].z += b.x; acc[i].w += b.y;
                }
            }

            // --- claim the stage buffer only now ---
            MBARRIER_WAIT_PARITY(EMPTY_BAR(sb, stage), (eph >> stage) & 1u);
            eph ^= (1u << stage);

            const uint32_t aT = sb + SM_A + stage * A_STAGE;

            #pragma unroll
            for (int i = 0; i < 2; i++) {
                const int r = wid * 2 + i;
                // self part: already fp16-packed, store as-is (cols 4l..4l+3)
                asm volatile("st.shared.v2.b32 [%0], {%1, %2};"
                             :: "r"(aT + sw_off(r, 4 * lane)),
                                "r"(sv[i].x), "r"(sv[i].y) : "memory");
                // neighbor mean part (cols 128 + 4l ..)
                __half2 p0 = __floats2half2_rn(acc[i].x * 0.1f, acc[i].y * 0.1f);
                __half2 p1 = __floats2half2_rn(acc[i].z * 0.1f, acc[i].w * 0.1f);
                const uint32_t m0 = *reinterpret_cast<uint32_t*>(&p0);
                const uint32_t m1 = *reinterpret_cast<uint32_t*>(&p1);
                asm volatile("st.shared.v2.b32 [%0], {%1, %2};"
                             :: "r"(aT + sw_off(r, 128 + 4 * lane)),
                                "r"(m0), "r"(m1) : "memory");
            }

            __threadfence_block();
            MBARRIER_ARRIVE(FULL_BAR(sb, stage));
            stage = (stage + 1) & (NSTAGE - 1);

            #pragma unroll
            for (int i = 0; i < 2; i++) { selfi[i] = nselfi[i]; idxv[i] = nidxv[i]; }
        }
    } else {
        // ============ CONSUMERS: 2 groups x 4 warps, 32x32 warp tiles ============
        const int cw    = wid - 16;         // 0..7
        const int group = cw >> 2;          // group g consumes tiles t==g (mod 2)
        const int nc    = (cw & 3) * 32;    // 0,32,64,96
        const uint32_t sW = sb + SM_W;

        const uint32_t a_row = (uint32_t)(lane & 15);
        const uint32_t a_sel = (uint32_t)(lane >> 4);          // 0/1
        const uint32_t b_row = (uint32_t)(nc + (lane & 7) + ((lane & 16) >> 1));
        const uint32_t b_sel = (uint32_t)((lane >> 3) & 1);    // 0/1
        const uint32_t a_x   = a_row & 7u;
        const uint32_t b_x   = b_row & 7u;
        const uint32_t aRowB = a_row * ROW_B;
        const uint32_t bRowB = b_row * ROW_B;

        // group g's stages: {g, g+2}, visited alternately; per-stage phases
        int stage = group;
        int phA = 0, phB = 0;
        int which = 0;

        for (int t = group; ; t += 2) {
            const long tile = (long)blockIdx.x + (long)t * gridDim.x;
            if (tile >= ntiles) break;
            const int base = (int)tile * BLK_M;

            const int ph = which ? phB : phA;
            MBARRIER_WAIT_PARITY(FULL_BAR(sb, stage), ph);

            const uint32_t aT = sb + SM_A + stage * A_STAGE;

            float acc[2][4][4];
            #pragma unroll
            for (int m = 0; m < 2; m++)
                #pragma unroll
                for (int n = 0; n < 4; n++)
                    #pragma unroll
                    for (int j = 0; j < 4; j++) acc[m][n][j] = 0.f;

            #pragma unroll
            for (int k = 0; k < K_DIM / 16; k++) {
                const uint32_t ac = (((2u * k + a_sel) ^ a_x) << 4);
                const uint32_t bc = (((2u * k + b_sel) ^ b_x) << 4);

                uint32_t a0[4], a1[4];
                ldsm_x4(a0, aT + aRowB + ac);
                ldsm_x4(a1, aT + aRowB + ac + 16 * ROW_B);

                uint32_t b0[4], b1[4];
                ldsm_x4(b0, sW + bRowB + bc);
                ldsm_x4(b1, sW + bRowB + bc + 16 * ROW_B);

                mma_f16(acc[0][0], a0, b0[0], b0[1]);
                mma_f16(acc[0][1], a0, b0[2], b0[3]);
                mma_f16(acc[0][2], a0, b1[0], b1[1]);
                mma_f16(acc[0][3], a0, b1[2], b1[3]);
                mma_f16(acc[1][0], a1, b0[0], b0[1]);
                mma_f16(acc[1][1], a1, b0[2], b0[3]);
                mma_f16(acc[1][2], a1, b1[0], b1[1]);
                mma_f16(acc[1][3], a1, b1[2], b1[3]);
            }

            MBARRIER_ARRIVE(EMPTY_BAR(sb, stage));
            if (which) phB ^= 1; else phA ^= 1;
            which ^= 1;
            stage = group + 2 * which;   // alternate {group, group+2}

            // epilogue from registers (stage already released)
            #pragma unroll
            for (int mi = 0; mi < 2; mi++) {
                const int r0 = base + mi * 16 + (lane >> 2);
                #pragma unroll
                for (int nt = 0; nt < 4; nt++) {
                    const int c = nc + nt * 8 + 2 * (lane & 3);
                    if (r0 < B) {
                        float2 v;
                        v.x = fmaxf(acc[mi][nt][0], 0.f);
                        v.y = fmaxf(acc[mi][nt][1], 0.f);
                        *reinterpret_cast<float2*>(out + (size_t)r0 * H_OUT + c) = v;
                    }
                    if (r0 + 8 < B) {
                        float2 v;
                        v.x = fmaxf(acc[mi][nt][2], 0.f);
                        v.y = fmaxf(acc[mi][nt][3], 0.f);
                        *reinterpret_cast<float2*>(out + (size_t)(r0 + 8) * H_OUT + c) = v;
                    }
                }
            }
        }
    }
}

// ---------------- launch ------------------------------------------------------
extern "C" void kernel_launch(void* const* d_in, const int* in_sizes, int n_in,
                              void* d_out, int out_size) {
    const int*   nodes  = (const int*)d_in[0];
    const int*   neigh  = (const int*)d_in[1];
    const float* feat   = (const float*)d_in[2];
    const float* weight = (const float*)d_in[3];
    float*       out    = (float*)d_out;
    const int B = in_sizes[0];
    const int ntiles = (B + BLK_M - 1) / BLK_M;

    // feature element count, clamped to the static fp16 table size
    int n_feat = in_sizes[2];
    const int max_elems = MAX_NODES * 128;
    if (n_feat > max_elems) n_feat = max_elems;

    sage_prep_weight<<<(K_DIM * H_OUT + 255) / 256, 256>>>(weight);
    sage_prep_feat<<<(n_feat / 8 + 255) / 256, 256>>>(feat, n_feat);

    cudaFuncSetAttribute(sage_main, cudaFuncAttributeMaxDynamicSharedMemorySize, SM_TOTAL);
    const int grid = (ntiles < 148) ? ntiles : 148;
    sage_main<<<grid, N_THREADS, SM_TOTAL>>>(nodes, neigh, out, B, ntiles);
}

// round 14
// speedup vs baseline: 1.2403x; 1.2403x over previous
#include <cuda_runtime.h>
#include <cuda_fp16.h>
#include <cstdint>

// ============================================================================
// GraphSAGE fused layer — sm_103 baseline-PTX, warp-specialized pipeline (R10).
//
//   out = relu(concat(feature[nodes], mean(feature[neigh_idx],1)) @ W)
//   B=50000, S=10, D=128, H=128, K=256.
//
// R10 = R8 structure + R9's producer rebalance, WITHOUT the fp16 feature
// table (its ~10us serial prep kernel ate the gain; gather was latency-bound,
// not byte-bound, so fp32 direct gather + 2x producer warps is the win):
//   * 768 threads: 16 producer warps (2 rows each, fp32 float4 gather, fp16
//     pack on store) + 8 consumer warps (2 groups x 4, 32x32 tiles)
//   * single fp16 mma product (fp32 accum), err ~3e-4 < 1e-3
//   * 4-stage A ring, XOR-swizzled 512B-pitch smem, persistent grid=148
// ============================================================================

static constexpr int BLK_M   = 32;
static constexpr int K_DIM   = 256;
static constexpr int H_OUT   = 128;
static constexpr int S_NEIGH = 10;
static constexpr int ROW_B   = 512;                   // 256 fp16, swizzled
static constexpr int W_BYTES = H_OUT * ROW_B;         // 65536
static constexpr int A_STAGE = BLK_M * ROW_B;         // 16384
static constexpr int NSTAGE  = 4;
static constexpr int N_THREADS = 768;

// smem layout
static constexpr int SM_W     = 0;
static constexpr int SM_A     = SM_W + W_BYTES;           // 65536
static constexpr int SM_BAR   = SM_A + NSTAGE * A_STAGE;  // 131072
static constexpr int SM_TOTAL = SM_BAR + 80;

__device__ __align__(16) unsigned char g_wh[W_BYTES];

// ---------------- helpers ----------------
__device__ __forceinline__ uint32_t smem_u32(const void* p) {
    uint32_t a;
    asm("{ .reg .u64 t; cvta.to.shared.u64 t, %1; cvt.u32.u64 %0, t; }"
        : "=r"(a) : "l"(p));
    return a;
}

// swizzled byte offset for element (row, kcol) in a 512B-pitch fp16 tile:
// 16B chunk index XORed with row%8
__host__ __device__ __forceinline__ uint32_t sw_off(int row, int kcol) {
    uint32_t byte  = (uint32_t)kcol * 2u;
    uint32_t chunk = (byte >> 4) ^ ((uint32_t)row & 7u);
    return (uint32_t)row * ROW_B + (chunk << 4) + (byte & 15u);
}

__device__ __forceinline__ void ldsm_x4(uint32_t (&d)[4], uint32_t addr) {
    asm volatile("ldmatrix.sync.aligned.m8n8.x4.shared.b16 {%0,%1,%2,%3}, [%4];"
                 : "=r"(d[0]), "=r"(d[1]), "=r"(d[2]), "=r"(d[3]) : "r"(addr));
}

__device__ __forceinline__ void mma_f16(float (&c)[4], const uint32_t (&a)[4],
                                        uint32_t b0, uint32_t b1) {
    asm volatile(
        "mma.sync.aligned.m16n8k16.row.col.f32.f16.f16.f32 "
        "{%0,%1,%2,%3}, {%4,%5,%6,%7}, {%8,%9}, {%0,%1,%2,%3};"
        : "+f"(c[0]), "+f"(c[1]), "+f"(c[2]), "+f"(c[3])
        : "r"(a[0]), "r"(a[1]), "r"(a[2]), "r"(a[3]), "r"(b0), "r"(b1));
}

#define MBARRIER_INIT(mbar, count) \
    asm volatile("mbarrier.init.shared.b64 [%0], %1;" \
                 :: "r"((uint32_t)(mbar)), "r"((uint32_t)(count)) : "memory")

#define MBARRIER_ARRIVE(mbar) \
    asm volatile("mbarrier.arrive.shared.b64 _, [%0];" \
                 :: "r"((uint32_t)(mbar)) : "memory")

#define MBARRIER_WAIT_PARITY(mbar, parity) do {                                  \
    uint32_t _m = (uint32_t)(mbar); uint32_t _p = (uint32_t)(parity);            \
    asm volatile(                                                                \
        "{\n\t.reg .pred P1;\n\t"                                                \
        "WAIT_LOOP_%=:\n\t"                                                      \
        "mbarrier.try_wait.parity.shared.b64 P1, [%0], %1;\n\t"                  \
        "@P1 bra.uni WAIT_DONE_%=;\n\t"                                          \
        "bra.uni WAIT_LOOP_%=;\n\t"                                              \
        "WAIT_DONE_%=:\n\t}"                                                     \
        :: "r"(_m), "r"(_p) : "memory");                                         \
} while (0)

#define FULL_BAR(sb, s)  ((sb) + SM_BAR + (s) * 16)
#define EMPTY_BAR(sb, s) ((sb) + SM_BAR + (s) * 16 + 8)

// ---------------- weight prep: transpose + fp16 + swizzle --------------------
__global__ void sage_prep_weight(const float* __restrict__ w) {
    int i = blockIdx.x * blockDim.x + threadIdx.x;
    if (i >= K_DIM * H_OUT) return;
    int k = i >> 7;        // weight row (0..255)
    int n = i & 127;       // weight col (0..127)
    *reinterpret_cast<__half*>(g_wh + sw_off(n, k)) = __float2half_rn(w[i]);
}

// ---------------- fused persistent warp-specialized kernel -------------------
__global__ __launch_bounds__(N_THREADS, 1)
void sage_main(const int* __restrict__ nodes,
               const int* __restrict__ neigh,
               const float* __restrict__ feat,
               float* __restrict__ out,
               int B, int ntiles) {
    extern __shared__ __align__(16) char smem[];
    const uint32_t sb   = smem_u32(smem);
    const int tid  = threadIdx.x;
    const int wid  = tid >> 5;
    const int lane = tid & 31;

    if (tid == 0) {
        #pragma unroll
        for (int s = 0; s < NSTAGE; s++) {
            MBARRIER_INIT(FULL_BAR(sb, s), 512);   // 16 producer warps arrive
            MBARRIER_INIT(EMPTY_BAR(sb, s), 128);  // 4 consumer warps arrive
        }
    }

    // copy weight into smem once (swizzle preserved by linear copy)
    {
        const uint4* s0 = reinterpret_cast<const uint4*>(g_wh);
        uint4* d0 = reinterpret_cast<uint4*>(smem + SM_W);
        for (int i = tid; i < W_BYTES / 16; i += N_THREADS) d0[i] = s0[i];
    }
    __syncthreads();

    if (wid < 16) {
        // ============ PRODUCERS: 16 warps, 2 rows each, fp32 gather ============
        // lane l covers cols 4l..4l+3 of a feature row (float4)
        const float4* feat4 = reinterpret_cast<const float4*>(feat);
        int stage = 0;
        uint32_t eph = 0xFu;   // per-stage empty parities (first pass free)

        // prologue: indices for first tile
        int selfi[2], idxv[2];
        {
            const int base = blockIdx.x * BLK_M;
            #pragma unroll
            for (int i = 0; i < 2; i++) {
                const int grow = base + wid * 2 + i;
                const int src = (grow < B) ? grow : 0;
                selfi[i] = __ldg(nodes + src);
                idxv[i] = (lane < S_NEIGH)
                          ? __ldg(neigh + (size_t)src * S_NEIGH + lane) : 0;
            }
        }

        for (int tile = blockIdx.x; tile < ntiles; tile += gridDim.x) {
            // --- feature loads for current tile (indices already resident) ---
            float4 sv[2], acc[2];
            #pragma unroll
            for (int i = 0; i < 2; i++) {
                sv[i] = __ldg(feat4 + (size_t)selfi[i] * 32 + lane);
                acc[i] = make_float4(0.f, 0.f, 0.f, 0.f);
            }

            // --- prefetch next tile's indices (hidden behind feature loads) ---
            int nselfi[2], nidxv[2];
            {
                const long nt = (long)tile + gridDim.x;
                const int nbase = (nt < ntiles) ? (int)nt * BLK_M : 0;
                #pragma unroll
                for (int i = 0; i < 2; i++) {
                    const int grow = nbase + wid * 2 + i;
                    const int src = (grow < B) ? grow : 0;
                    nselfi[i] = __ldg(nodes + src);
                    nidxv[i] = (lane < S_NEIGH)
                               ? __ldg(neigh + (size_t)src * S_NEIGH + lane) : 0;
                }
            }

            #pragma unroll
            for (int s = 0; s < S_NEIGH; s++) {
                #pragma unroll
                for (int i = 0; i < 2; i++) {
                    const int ni = __shfl_sync(0xffffffffu, idxv[i], s);
                    const float4 v = __ldg(feat4 + (size_t)ni * 32 + lane);
                    acc[i].x += v.x; acc[i].y += v.y;
                    acc[i].z += v.z; acc[i].w += v.w;
                }
            }

            // --- claim the stage buffer only now ---
            MBARRIER_WAIT_PARITY(EMPTY_BAR(sb, stage), (eph >> stage) & 1u);
            eph ^= (1u << stage);

            const uint32_t aT = sb + SM_A + stage * A_STAGE;

            #pragma unroll
            for (int i = 0; i < 2; i++) {
                const int r = wid * 2 + i;
                // self part (cols 4l..4l+3)
                __half2 s0 = __floats2half2_rn(sv[i].x, sv[i].y);
                __half2 s1 = __floats2half2_rn(sv[i].z, sv[i].w);
                const uint32_t sx = *reinterpret_cast<uint32_t*>(&s0);
                const uint32_t sy = *reinterpret_cast<uint32_t*>(&s1);
                asm volatile("st.shared.v2.b32 [%0], {%1, %2};"
                             :: "r"(aT + sw_off(r, 4 * lane)), "r"(sx), "r"(sy)
                             : "memory");
                // neighbor mean part (cols 128 + 4l ..)
                __half2 p0 = __floats2half2_rn(acc[i].x * 0.1f, acc[i].y * 0.1f);
                __half2 p1 = __floats2half2_rn(acc[i].z * 0.1f, acc[i].w * 0.1f);
                const uint32_t m0 = *reinterpret_cast<uint32_t*>(&p0);
                const uint32_t m1 = *reinterpret_cast<uint32_t*>(&p1);
                asm volatile("st.shared.v2.b32 [%0], {%1, %2};"
                             :: "r"(aT + sw_off(r, 128 + 4 * lane)), "r"(m0), "r"(m1)
                             : "memory");
            }

            __threadfence_block();
            MBARRIER_ARRIVE(FULL_BAR(sb, stage));
            stage = (stage + 1) & (NSTAGE - 1);

            #pragma unroll
            for (int i = 0; i < 2; i++) { selfi[i] = nselfi[i]; idxv[i] = nidxv[i]; }
        }
    } else {
        // ============ CONSUMERS: 2 groups x 4 warps, 32x32 warp tiles ============
        const int cw    = wid - 16;         // 0..7
        const int group = cw >> 2;          // group g consumes tiles t==g (mod 2)
        const int nc    = (cw & 3) * 32;    // 0,32,64,96
        const uint32_t sW = sb + SM_W;

        const uint32_t a_row = (uint32_t)(lane & 15);
        const uint32_t a_sel = (uint32_t)(lane >> 4);          // 0/1
        const uint32_t b_row = (uint32_t)(nc + (lane & 7) + ((lane & 16) >> 1));
        const uint32_t b_sel = (uint32_t)((lane >> 3) & 1);    // 0/1
        const uint32_t a_x   = a_row & 7u;
        const uint32_t b_x   = b_row & 7u;
        const uint32_t aRowB = a_row * ROW_B;
        const uint32_t bRowB = b_row * ROW_B;

        // group g's stages: {g, g+2}, visited alternately; per-stage phases
        int stage = group;
        int phA = 0, phB = 0;
        int which = 0;

        for (int t = group; ; t += 2) {
            const long tile = (long)blockIdx.x + (long)t * gridDim.x;
            if (tile >= ntiles) break;
            const int base = (int)tile * BLK_M;

            const int ph = which ? phB : phA;
            MBARRIER_WAIT_PARITY(FULL_BAR(sb, stage), ph);

            const uint32_t aT = sb + SM_A + stage * A_STAGE;

            float acc[2][4][4];
            #pragma unroll
            for (int m = 0; m < 2; m++)
                #pragma unroll
                for (int n = 0; n < 4; n++)
                    #pragma unroll
                    for (int j = 0; j < 4; j++) acc[m][n][j] = 0.f;

            #pragma unroll
            for (int k = 0; k < K_DIM / 16; k++) {
                const uint32_t ac = (((2u * k + a_sel) ^ a_x) << 4);
                const uint32_t bc = (((2u * k + b_sel) ^ b_x) << 4);

                uint32_t a0[4], a1[4];
                ldsm_x4(a0, aT + aRowB + ac);
                ldsm_x4(a1, aT + aRowB + ac + 16 * ROW_B);

                uint32_t b0[4], b1[4];
                ldsm_x4(b0, sW + bRowB + bc);
                ldsm_x4(b1, sW + bRowB + bc + 16 * ROW_B);

                mma_f16(acc[0][0], a0, b0[0], b0[1]);
                mma_f16(acc[0][1], a0, b0[2], b0[3]);
                mma_f16(acc[0][2], a0, b1[0], b1[1]);
                mma_f16(acc[0][3], a0, b1[2], b1[3]);
                mma_f16(acc[1][0], a1, b0[0], b0[1]);
                mma_f16(acc[1][1], a1, b0[2], b0[3]);
                mma_f16(acc[1][2], a1, b1[0], b1[1]);
                mma_f16(acc[1][3], a1, b1[2], b1[3]);
            }

            MBARRIER_ARRIVE(EMPTY_BAR(sb, stage));
            if (which) phB ^= 1; else phA ^= 1;
            which ^= 1;
            stage = group + 2 * which;   // alternate {group, group+2}

            // epilogue from registers (stage already released)
            #pragma unroll
            for (int mi = 0; mi < 2; mi++) {
                const int r0 = base + mi * 16 + (lane >> 2);
                #pragma unroll
                for (int nt = 0; nt < 4; nt++) {
                    const int c = nc + nt * 8 + 2 * (lane & 3);
                    if (r0 < B) {
                        float2 v;
                        v.x = fmaxf(acc[mi][nt][0], 0.f);
                        v.y = fmaxf(acc[mi][nt][1], 0.f);
                        *reinterpret_cast<float2*>(out + (size_t)r0 * H_OUT + c) = v;
                    }
                    if (r0 + 8 < B) {
                        float2 v;
                        v.x = fmaxf(acc[mi][nt][2], 0.f);
                        v.y = fmaxf(acc[mi][nt][3], 0.f);
                        *reinterpret_cast<float2*>(out + (size_t)(r0 + 8) * H_OUT + c) = v;
                    }
                }
            }
        }
    }
}

// ---------------- launch ------------------------------------------------------
extern "C" void kernel_launch(void* const* d_in, const int* in_sizes, int n_in,
                              void* d_out, int out_size) {
    const int*   nodes  = (const int*)d_in[0];
    const int*   neigh  = (const int*)d_in[1];
    const float* feat   = (const float*)d_in[2];
    const float* weight = (const float*)d_in[3];
    float*       out    = (float*)d_out;
    const int B = in_sizes[0];
    const int ntiles = (B + BLK_M - 1) / BLK_M;

    sage_prep_weight<<<(K_DIM * H_OUT + 255) / 256, 256>>>(weight);

    cudaFuncSetAttribute(sage_main, cudaFuncAttributeMaxDynamicSharedMemorySize, SM_TOTAL);
    const int grid = (ntiles < 148) ? ntiles : 148;
    sage_main<<<grid, N_THREADS, SM_TOTAL>>>(nodes, neigh, feat, out, B, ntiles);
}